// round 15
// baseline (speedup 1.0000x reference)
#include <cuda_runtime.h>
#include <cstdint>

// ---------------------------------------------------------------------------
// BMM_AB_I8_E_F32: C[b,m,n] = alpha * sum_k a[b,m,k]*b[b,k,n]
// B=16, M=1024, K=4096, N=4096.
//
// R2:  PTX target sm_103 (no 'a') -> no tcgen05; legacy mma.sync only.
// R6:  inputs serialized int32 -> int8 scratch conversion pre-pass.
// R8:  legacy IMMA pipe ~267 MACs/cyc/SM. dp4a (fma pipe) rt=1 -> 512/cyc/SM.
// R10/R12: warp-specialized IMMA|dp4a. Profile shows BOTH pipes finish their
//      work at full rate but the chunk is 2x either: the 2 dp4a warps/SMSP
//      are latency-bound (no reg headroom to pipeline B loads, too few warps
//      to hide LDS latency). Specialization starves the latency-hiding.
// R13: FUSED-ROLE warps, separate accumulators. Every warp: IMMA strip
//      m16n64 over rows[0:64) + dp4a 8 rows x 128 cols over rows[64:128).
//      1 MMA interleaved per 40 dp4a issues; 4 such warps per SMSP hide
//      each other's stalls. 64 accums + av[16] ~ 105 regs.
// ---------------------------------------------------------------------------

#define BATCH   16
#define MDIM    1024
#define KDIM    4096
#define NDIM    4096

#define MT      128
#define NT      128
#define KT      64            // K bytes per pipeline chunk
#define KCHUNKS (KDIM / KT)   // 64
#define THREADS 256
#define NSTAGE  3

#define A_STRIDE 80                     // bytes per m-row in SMEM
#define A_STAGE  (128 * A_STRIDE)       // 10240
#define B_WORDS  132                    // k-word row stride in words
#define B_STAGE  (16 * B_WORDS * 4)     // 8448

#define OFF_A    0
#define OFF_B    (NSTAGE * A_STAGE)                 // 30720
#define SMEM_TOTAL (OFF_B + NSTAGE * B_STAGE)       // 56064

#define A_ELEMS ((size_t)BATCH * MDIM * KDIM)   // 67108864
#define B_ELEMS ((size_t)BATCH * KDIM * NDIM)   // 268435456
#define KWTOT   ((size_t)BATCH * (KDIM / 4))    // 16384 global k-word rows

__device__ int8_t g_a8[A_ELEMS];
__device__ int8_t g_bt[B_ELEMS];   // B k-word-major: word[gkw*N + n] = b[4gkw..+3][n]

// ---------------- conversions ----------------
__device__ __forceinline__ uint32_t pack4(int4 x) {
    uint32_t lo = __byte_perm((uint32_t)x.x, (uint32_t)x.y, 0x0040);
    uint32_t hi = __byte_perm((uint32_t)x.z, (uint32_t)x.w, 0x0040);
    return __byte_perm(lo, hi, 0x5410);
}

__global__ void __launch_bounds__(256)
conv_a_kernel(const int4* __restrict__ src, uint4* __restrict__ dst, long n16) {
    const long stride = (long)gridDim.x * blockDim.x;
    for (long i = (long)blockIdx.x * blockDim.x + threadIdx.x; i < n16; i += stride) {
        uint4 v;
        v.x = pack4(src[i * 4 + 0]);
        v.y = pack4(src[i * 4 + 1]);
        v.z = pack4(src[i * 4 + 2]);
        v.w = pack4(src[i * 4 + 3]);
        dst[i] = v;
    }
}

__global__ void __launch_bounds__(256)
conv_b_kernel(const int4* __restrict__ src, uint4* __restrict__ dst) {
    const long total = (long)KWTOT * (NDIM / 4);     // 16.7M
    const long stride = (long)gridDim.x * blockDim.x;
    for (long i = (long)blockIdx.x * blockDim.x + threadIdx.x; i < total; i += stride) {
        const long gkw = i >> 10;
        const int  n4  = (int)(i & 1023);
        const int4* s = src + (gkw * 4) * (NDIM / 4) + n4;
        int4 r0 = s[0];
        int4 r1 = s[NDIM / 4];
        int4 r2 = s[2 * (NDIM / 4)];
        int4 r3 = s[3 * (NDIM / 4)];
        uint32_t w0 = pack4(make_int4(r0.x, r1.x, r2.x, r3.x));
        uint32_t w1 = pack4(make_int4(r0.y, r1.y, r2.y, r3.y));
        uint32_t w2 = pack4(make_int4(r0.z, r1.z, r2.z, r3.z));
        uint32_t w3 = pack4(make_int4(r0.w, r1.w, r2.w, r3.w));
        dst[gkw * (NDIM / 4) + n4] = make_uint4(w0, w1, w2, w3);
    }
}

// ---------------- GEMM helpers ----------------
__device__ __forceinline__ uint32_t smem_u32(const void* p) {
    uint32_t a;
    asm("{ .reg .u64 t; cvta.to.shared.u64 t, %1; cvt.u32.u64 %0, t; }"
        : "=r"(a) : "l"(p));
    return a;
}

__device__ __forceinline__ void cpa16(uint32_t dst, const void* src) {
    asm volatile("cp.async.cg.shared.global [%0], [%1], 16;" :: "r"(dst), "l"(src));
}

__device__ __forceinline__ void ldmA(uint32_t a[4], uint32_t addr) {
    asm volatile("ldmatrix.sync.aligned.m8n8.x4.shared.b16 {%0,%1,%2,%3}, [%4];"
                 : "=r"(a[0]), "=r"(a[1]), "=r"(a[2]), "=r"(a[3]) : "r"(addr));
}

__device__ __forceinline__ uint32_t lds32(uint32_t addr) {
    uint32_t v;
    asm volatile("ld.shared.b32 %0, [%1];" : "=r"(v) : "r"(addr));
    return v;
}

__device__ __forceinline__ uint2 lds64(uint32_t addr) {
    uint2 v;
    asm volatile("ld.shared.v2.b32 {%0,%1}, [%2];" : "=r"(v.x), "=r"(v.y) : "r"(addr));
    return v;
}

__device__ __forceinline__ uint4 lds128(uint32_t addr) {
    uint4 v;
    asm volatile("ld.shared.v4.b32 {%0,%1,%2,%3}, [%4];"
                 : "=r"(v.x), "=r"(v.y), "=r"(v.z), "=r"(v.w) : "r"(addr));
    return v;
}

__device__ __forceinline__ void mma_s8(int c[4], const uint32_t a[4],
                                       uint32_t b0, uint32_t b1) {
    asm volatile(
        "mma.sync.aligned.m16n8k32.row.col.s32.s8.s8.s32 "
        "{%0,%1,%2,%3}, {%4,%5,%6,%7}, {%8,%9}, {%0,%1,%2,%3};"
        : "+r"(c[0]), "+r"(c[1]), "+r"(c[2]), "+r"(c[3])
        : "r"(a[0]), "r"(a[1]), "r"(a[2]), "r"(a[3]), "r"(b0), "r"(b1));
}

__device__ __forceinline__ void dp4a(int& c, uint32_t a, uint32_t b) {
    asm volatile("dp4a.s32.s32 %0, %1, %2, %0;" : "+r"(c) : "r"(a), "r"(b));
}

__global__ void __launch_bounds__(THREADS, 2)
bmm_i8_kernel(const float* __restrict__ alpha_p, float* __restrict__ out,
              int batch0)
{
    extern __shared__ char smem[];
    const uint32_t sbase = smem_u32(smem);

    const int tid  = threadIdx.x;
    const int wid  = tid >> 5;
    const int lane = tid & 31;
    const int g    = lane >> 2;
    const int tig  = lane & 3;

    // 256 tiles per batch (8 m x 32 n); this launch covers 4 batches
    const int bid   = blockIdx.x;
    const int batch = batch0 + (bid >> 8);
    const int rem   = bid & 255;
    const int m0    = (rem >> 5) * MT;
    const int n0    = (rem & 31) * NT;

    const int8_t*   aB  = g_a8 + (size_t)batch * MDIM * KDIM + (size_t)m0 * KDIM;
    const uint32_t* btB = reinterpret_cast<const uint32_t*>(g_bt)
                          + (size_t)batch * (KDIM / 4) * NDIM + n0;
    float* outB = out + (size_t)batch * MDIM * NDIM;

    // Fused roles per warp:
    //  IMMA: strip s = wid>>1 (rows 16s..16s+16 of [0:64)), n-half h = wid&1
    //  dp4a: row 64 + 8*wid + g, all 128 cols (32 per thread via tig/nj)
    const int s = wid >> 1;
    const int h = wid & 1;

    // cp.async indices
    const int ar0 = tid >> 2;                   // A rows 0..63 (+64)
    const int ac0 = (tid & 3) << 4;
    const int brw = tid >> 5;                   // B k-word rows 0..7 (+8)
    const int bcw = (tid & 31) << 4;

    int ct[8][4];       // IMMA accums: ni 0..7
    int cd[8][4];       // dp4a accums: nj 0..7 (cols tig*4+16nj .. +3)
#pragma unroll
    for (int i = 0; i < 8; i++)
#pragma unroll
        for (int r = 0; r < 4; r++) { ct[i][r] = 0; cd[i][r] = 0; }

    auto issue_chunk = [&](int chunk, int stg) {
        const int kk = chunk * KT;
        const uint32_t sA = sbase + OFF_A + stg * A_STAGE;
        cpa16(sA + ar0 * A_STRIDE + ac0,        aB + (size_t)ar0 * KDIM + kk + ac0);
        cpa16(sA + (ar0 + 64) * A_STRIDE + ac0, aB + (size_t)(ar0 + 64) * KDIM + kk + ac0);
        const uint32_t sB = sbase + OFF_B + stg * B_STAGE;
        const int kw0 = chunk * 16;
        cpa16(sB + brw * (B_WORDS * 4) + bcw,
              (const char*)(btB + (size_t)(kw0 + brw) * NDIM) + bcw);
        cpa16(sB + (brw + 8) * (B_WORDS * 4) + bcw,
              (const char*)(btB + (size_t)(kw0 + brw + 8) * NDIM) + bcw);
    };

    auto compute = [&](int stg) {
        const uint32_t baseA = sbase + OFF_A + stg * A_STAGE;
        const uint32_t baseB = sbase + OFF_B + stg * B_STAGE;

        // dp4a A row: cache all 16 k-words of this thread's row in regs
        const uint32_t aRow = baseA + (uint32_t)(64 + 8 * wid + g) * A_STRIDE;
        uint2 av[8];
#pragma unroll
        for (int i = 0; i < 8; i++) av[i] = lds64(aRow + (uint32_t)(i * 8));

        const int mrow = s * 16 + (lane & 15);
        const int khl  = lane >> 4;
#pragma unroll
        for (int ks = 0; ks < 2; ks++) {
            uint32_t af[4];
            ldmA(af, baseA + (uint32_t)mrow * A_STRIDE + (uint32_t)((ks * 2 + khl) * 16));
#pragma unroll
            for (int ni = 0; ni < 8; ni++) {
                // --- one IMMA (tensor pipe) ---
                const int col = h * 64 + ni * 8 + g;
                const int kwb = ks * 8 + tig;
                const uint32_t b0 = lds32(baseB + (uint32_t)((kwb)     * B_WORDS + col) * 4);
                const uint32_t b1 = lds32(baseB + (uint32_t)((kwb + 4) * B_WORDS + col) * 4);
                mma_s8(ct[ni], af, b0, b1);

                // --- dp4a block for k-word kw = ks*8+ni (fma pipe) ---
                const int kw = ks * 8 + ni;
                const uint32_t avw = (kw & 1) ? av[kw >> 1].y : av[kw >> 1].x;
                const uint32_t bRow = baseB + (uint32_t)(kw * B_WORDS) * 4;
#pragma unroll
                for (int nj = 0; nj < 8; nj++) {
                    uint4 b = lds128(bRow + (uint32_t)((tig * 4 + nj * 16) * 4));
                    dp4a(cd[nj][0], avw, b.x);
                    dp4a(cd[nj][1], avw, b.y);
                    dp4a(cd[nj][2], avw, b.z);
                    dp4a(cd[nj][3], avw, b.w);
                }
            }
        }
    };

    // ---- prologue ----
    issue_chunk(0, 0);
    asm volatile("cp.async.commit_group;" ::: "memory");
    issue_chunk(1, 1);
    asm volatile("cp.async.commit_group;" ::: "memory");

    // ---- mainloop: one barrier per chunk ----
    int stg = 0;
    for (int i = 0; i < KCHUNKS; i++) {
        if (i + 1 < KCHUNKS)
            asm volatile("cp.async.wait_group 1;" ::: "memory");
        else
            asm volatile("cp.async.wait_group 0;" ::: "memory");
        __syncthreads();

        if (i + 2 < KCHUNKS) {
            int fstg = stg + 2; if (fstg >= NSTAGE) fstg -= NSTAGE;
            issue_chunk(i + 2, fstg);
            asm volatile("cp.async.commit_group;" ::: "memory");
        }

        compute(stg);

        if (++stg == NSTAGE) stg = 0;
    }

    // ---- epilogue ----
    const float alpha = *alpha_p;
    // IMMA part: rows m0 + 16s + g (+8), cols n0 + 64h + ni*8 + 2tig
#pragma unroll
    for (int ni = 0; ni < 8; ni++) {
        const int row = m0 + s * 16 + g;
        const int col = n0 + h * 64 + ni * 8 + 2 * tig;
        float2 v0, v1;
        v0.x = (float)ct[ni][0] * alpha;
        v0.y = (float)ct[ni][1] * alpha;
        v1.x = (float)ct[ni][2] * alpha;
        v1.y = (float)ct[ni][3] * alpha;
        *reinterpret_cast<float2*>(outB + (size_t)row * NDIM + col) = v0;
        *reinterpret_cast<float2*>(outB + (size_t)(row + 8) * NDIM + col) = v1;
    }
    // dp4a part: row m0 + 64 + 8*wid + g, cols n0 + tig*4 + nj*16
    {
        const int row = m0 + 64 + 8 * wid + g;
#pragma unroll
        for (int nj = 0; nj < 8; nj++) {
            const int col = n0 + tig * 4 + nj * 16;
            float4 v;
            v.x = (float)cd[nj][0] * alpha;
            v.y = (float)cd[nj][1] * alpha;
            v.z = (float)cd[nj][2] * alpha;
            v.w = (float)cd[nj][3] * alpha;
            *reinterpret_cast<float4*>(outB + (size_t)row * NDIM + col) = v;
        }
    }
}

extern "C" void kernel_launch(void* const* d_in, const int* in_sizes, int n_in,
                              void* d_out, int out_size) {
    const int* a32 = (const int*)d_in[0];
    const int* b32 = (const int*)d_in[1];
    const float* alpha = (const float*)(n_in > 2 ? d_in[2] : d_in[1]);
    for (int i = 0; i < n_in; i++) {
        const long long sz = in_sizes[i];
        if (sz == (long long)A_ELEMS)      a32 = (const int*)d_in[i];
        else if (sz == (long long)B_ELEMS) b32 = (const int*)d_in[i];
        else if (sz == 1)                  alpha = (const float*)d_in[i];
    }
    float* out = (float*)d_out;

    int8_t* a8 = nullptr;
    int8_t* bt = nullptr;
    cudaGetSymbolAddress((void**)&a8, g_a8);
    cudaGetSymbolAddress((void**)&bt, g_bt);

    static int smem_set = 0;
    if (!smem_set) {
        cudaFuncSetAttribute(bmm_i8_kernel,
                             cudaFuncAttributeMaxDynamicSharedMemorySize, SMEM_TOTAL);
        smem_set = 1;
    }

    conv_a_kernel<<<2048, 256>>>((const int4*)a32, (uint4*)a8, (long)(A_ELEMS / 16));
    conv_b_kernel<<<4096, 256>>>((const int4*)b32, (uint4*)bt);

    const int grid = 4 * (MDIM / MT) * (NDIM / NT);  // 1024 CTAs per launch
    for (int g = 0; g < 4; g++)
        bmm_i8_kernel<<<grid, THREADS, SMEM_TOTAL>>>(alpha, out, g * 4);
}

// round 16
// speedup vs baseline: 1.5676x; 1.5676x over previous
#include <cuda_runtime.h>
#include <cstdint>

// ---------------------------------------------------------------------------
// BMM_AB_I8_E_F32: C[b,m,n] = alpha * sum_k a[b,m,k]*b[b,k,n]
// B=16, M=1024, K=4096, N=4096.
//
// R2:  PTX target sm_103 (no 'a') -> no tcgen05; legacy mma.sync only.
// R6:  inputs serialized int32 -> int8 scratch conversion pre-pass.
// R8:  legacy IMMA pipe ~267 MACs/cyc/SM. dp4a (fma pipe) rt=1.
// R13: fused-role warps -> SMEM-bandwidth bound (L1 90%). Reverted.
// R16: specialization with model-fitted split: IMMA 61.4 cyc/row,
//      dp4a 83 cyc/row (latency-limited) -> balance at 80 IMMA / 48 dp4a.
//      IMMA loop mi-outer (live regs ~100); dp4a 48 accums (reg headroom
//      for load pipelining). B pre-transposed in conversion pass.
// ---------------------------------------------------------------------------

#define BATCH   16
#define MDIM    1024
#define KDIM    4096
#define NDIM    4096

#define MT      128
#define NT      128
#define KT      64            // K bytes per pipeline chunk
#define KCHUNKS (KDIM / KT)   // 64
#define THREADS 256
#define NSTAGE  3

#define A_STRIDE 80                     // bytes per m-row in SMEM
#define A_STAGE  (128 * A_STRIDE)       // 10240
#define B_WORDS  132                    // k-word row stride in words
#define B_STAGE  (16 * B_WORDS * 4)     // 8448

#define OFF_A    0
#define OFF_B    (NSTAGE * A_STAGE)                 // 30720
#define SMEM_TOTAL (OFF_B + NSTAGE * B_STAGE)       // 56064

#define A_ELEMS ((size_t)BATCH * MDIM * KDIM)   // 67108864
#define B_ELEMS ((size_t)BATCH * KDIM * NDIM)   // 268435456
#define KWTOT   ((size_t)BATCH * (KDIM / 4))    // 16384 global k-word rows

__device__ int8_t g_a8[A_ELEMS];
__device__ int8_t g_bt[B_ELEMS];   // B k-word-major: word[gkw*N + n] = b[4gkw..+3][n]

// ---------------- conversions ----------------
__device__ __forceinline__ uint32_t pack4(int4 x) {
    uint32_t lo = __byte_perm((uint32_t)x.x, (uint32_t)x.y, 0x0040);
    uint32_t hi = __byte_perm((uint32_t)x.z, (uint32_t)x.w, 0x0040);
    return __byte_perm(lo, hi, 0x5410);
}

__global__ void __launch_bounds__(256)
conv_a_kernel(const int4* __restrict__ src, uint4* __restrict__ dst, long n16) {
    const long stride = (long)gridDim.x * blockDim.x;
    for (long i = (long)blockIdx.x * blockDim.x + threadIdx.x; i < n16; i += stride) {
        uint4 v;
        v.x = pack4(src[i * 4 + 0]);
        v.y = pack4(src[i * 4 + 1]);
        v.z = pack4(src[i * 4 + 2]);
        v.w = pack4(src[i * 4 + 3]);
        dst[i] = v;
    }
}

__global__ void __launch_bounds__(256)
conv_b_kernel(const int4* __restrict__ src, uint4* __restrict__ dst) {
    const long total = (long)KWTOT * (NDIM / 4);     // 16.7M
    const long stride = (long)gridDim.x * blockDim.x;
    for (long i = (long)blockIdx.x * blockDim.x + threadIdx.x; i < total; i += stride) {
        const long gkw = i >> 10;
        const int  n4  = (int)(i & 1023);
        const int4* s = src + (gkw * 4) * (NDIM / 4) + n4;
        int4 r0 = s[0];
        int4 r1 = s[NDIM / 4];
        int4 r2 = s[2 * (NDIM / 4)];
        int4 r3 = s[3 * (NDIM / 4)];
        uint32_t w0 = pack4(make_int4(r0.x, r1.x, r2.x, r3.x));
        uint32_t w1 = pack4(make_int4(r0.y, r1.y, r2.y, r3.y));
        uint32_t w2 = pack4(make_int4(r0.z, r1.z, r2.z, r3.z));
        uint32_t w3 = pack4(make_int4(r0.w, r1.w, r2.w, r3.w));
        dst[gkw * (NDIM / 4) + n4] = make_uint4(w0, w1, w2, w3);
    }
}

// ---------------- GEMM helpers ----------------
__device__ __forceinline__ uint32_t smem_u32(const void* p) {
    uint32_t a;
    asm("{ .reg .u64 t; cvta.to.shared.u64 t, %1; cvt.u32.u64 %0, t; }"
        : "=r"(a) : "l"(p));
    return a;
}

__device__ __forceinline__ void cpa16(uint32_t dst, const void* src) {
    asm volatile("cp.async.cg.shared.global [%0], [%1], 16;" :: "r"(dst), "l"(src));
}

__device__ __forceinline__ void ldmA(uint32_t a[4], uint32_t addr) {
    asm volatile("ldmatrix.sync.aligned.m8n8.x4.shared.b16 {%0,%1,%2,%3}, [%4];"
                 : "=r"(a[0]), "=r"(a[1]), "=r"(a[2]), "=r"(a[3]) : "r"(addr));
}

__device__ __forceinline__ uint32_t lds32(uint32_t addr) {
    uint32_t v;
    asm volatile("ld.shared.b32 %0, [%1];" : "=r"(v) : "r"(addr));
    return v;
}

__device__ __forceinline__ uint2 lds64(uint32_t addr) {
    uint2 v;
    asm volatile("ld.shared.v2.b32 {%0,%1}, [%2];" : "=r"(v.x), "=r"(v.y) : "r"(addr));
    return v;
}

__device__ __forceinline__ uint4 lds128(uint32_t addr) {
    uint4 v;
    asm volatile("ld.shared.v4.b32 {%0,%1,%2,%3}, [%4];"
                 : "=r"(v.x), "=r"(v.y), "=r"(v.z), "=r"(v.w) : "r"(addr));
    return v;
}

__device__ __forceinline__ void mma_s8(int c[4], const uint32_t a[4],
                                       uint32_t b0, uint32_t b1) {
    asm volatile(
        "mma.sync.aligned.m16n8k32.row.col.s32.s8.s8.s32 "
        "{%0,%1,%2,%3}, {%4,%5,%6,%7}, {%8,%9}, {%0,%1,%2,%3};"
        : "+r"(c[0]), "+r"(c[1]), "+r"(c[2]), "+r"(c[3])
        : "r"(a[0]), "r"(a[1]), "r"(a[2]), "r"(a[3]), "r"(b0), "r"(b1));
}

__device__ __forceinline__ void dp4a(int& c, uint32_t a, uint32_t b) {
    asm volatile("dp4a.s32.s32 %0, %1, %2, %0;" : "+r"(c) : "r"(a), "r"(b));
}

__global__ void __launch_bounds__(THREADS, 2)
bmm_i8_kernel(const float* __restrict__ alpha_p, float* __restrict__ out,
              int batch0)
{
    extern __shared__ char smem[];
    const uint32_t sbase = smem_u32(smem);

    const int tid  = threadIdx.x;
    const int wid  = tid >> 5;
    const int lane = tid & 31;
    const int g    = lane >> 2;
    const int tig  = lane & 3;

    // 256 tiles per batch (8 m x 32 n); this launch covers 4 batches
    const int bid   = blockIdx.x;
    const int batch = batch0 + (bid >> 8);
    const int rem   = bid & 255;
    const int m0    = (rem >> 5) * MT;
    const int n0    = (rem & 31) * NT;

    const int8_t*   aB  = g_a8 + (size_t)batch * MDIM * KDIM + (size_t)m0 * KDIM;
    const uint32_t* btB = reinterpret_cast<const uint32_t*>(g_bt)
                          + (size_t)batch * (KDIM / 4) * NDIM + n0;
    float* outB = out + (size_t)batch * MDIM * NDIM;

    // Roles (1 of each per SMSP per CTA):
    //  warps 0-3: IMMA on m[0:80), warp w -> cols w*32..+32 (5 m16 strips)
    //  warps 4-7: dp4a on m[80:128), 2x2 grid of 24m x 64n
    const int wsub = wid & 3;
    const int dmB  = 80 + (wsub >> 1) * 24;     // dp4a row base
    const int dnB  = (wsub & 1) * 64;           // dp4a col base

    // cp.async indices
    const int ar0 = tid >> 2;                   // A rows 0..63 (+64)
    const int ac0 = (tid & 3) << 4;
    const int brw = tid >> 5;                   // B k-word rows 0..7 (+8)
    const int bcw = (tid & 31) << 4;

    int cacc[5][4][4];                          // IMMA all 5; dp4a first 3
#pragma unroll
    for (int i = 0; i < 5; i++)
#pragma unroll
        for (int j = 0; j < 4; j++)
#pragma unroll
            for (int r = 0; r < 4; r++) cacc[i][j][r] = 0;

    auto issue_chunk = [&](int chunk, int stg) {
        const int kk = chunk * KT;
        const uint32_t sA = sbase + OFF_A + stg * A_STAGE;
        cpa16(sA + ar0 * A_STRIDE + ac0,        aB + (size_t)ar0 * KDIM + kk + ac0);
        cpa16(sA + (ar0 + 64) * A_STRIDE + ac0, aB + (size_t)(ar0 + 64) * KDIM + kk + ac0);
        const uint32_t sB = sbase + OFF_B + stg * B_STAGE;
        const int kw0 = chunk * 16;
        cpa16(sB + brw * (B_WORDS * 4) + bcw,
              (const char*)(btB + (size_t)(kw0 + brw) * NDIM) + bcw);
        cpa16(sB + (brw + 8) * (B_WORDS * 4) + bcw,
              (const char*)(btB + (size_t)(kw0 + brw + 8) * NDIM) + bcw);
    };

    // IMMA warps: 80m x 32n per warp, 40 m16n8k32 per chunk.
    // mi-outer / ni-inner keeps only one af[4] live (total ~100 regs).
    auto compute_imma = [&](int stg) {
        const uint32_t baseA = sbase + OFF_A + stg * A_STAGE;
        const uint32_t baseB = sbase + OFF_B + stg * B_STAGE;
        const int mrow = lane & 15;
        const int khl  = lane >> 4;
#pragma unroll
        for (int ks = 0; ks < 2; ks++) {
            uint32_t bf[4][2];
#pragma unroll
            for (int ni = 0; ni < 4; ni++) {
                const int col = wsub * 32 + ni * 8 + g;
                const int kwb = ks * 8 + tig;
                bf[ni][0] = lds32(baseB + (uint32_t)((kwb)     * B_WORDS + col) * 4);
                bf[ni][1] = lds32(baseB + (uint32_t)((kwb + 4) * B_WORDS + col) * 4);
            }
#pragma unroll
            for (int mi = 0; mi < 5; mi++) {
                uint32_t af[4];
                ldmA(af, baseA + (uint32_t)(mrow + mi * 16) * A_STRIDE
                               + (uint32_t)((ks * 2 + khl) * 16));
#pragma unroll
                for (int ni = 0; ni < 4; ni++)
                    mma_s8(cacc[mi][ni], af, bf[ni][0], bf[ni][1]);
            }
        }
    };

    // dp4a warps: 24m x 64n per warp; 768 dp4a + 88 LDS per thread per chunk.
    auto compute_dp4a = [&](int stg) {
        const uint32_t baseA = sbase + OFF_A + stg * A_STAGE;
        const uint32_t baseB = sbase + OFF_B + stg * B_STAGE;
#pragma unroll
        for (int kwp = 0; kwp < 8; kwp++) {
            const int kw = 2 * kwp;
            uint2 aw[3];
#pragma unroll
            for (int mb = 0; mb < 3; mb++)
                aw[mb] = lds64(baseA + (uint32_t)(dmB + mb * 8 + g) * A_STRIDE
                                     + (uint32_t)(kw * 4));
#pragma unroll
            for (int ni = 0; ni < 4; ni++) {
                const int colw = dnB + ni * 16 + tig * 4;
                uint4 b0 = lds128(baseB + (uint32_t)((kw)     * B_WORDS + colw) * 4);
                uint4 b1 = lds128(baseB + (uint32_t)((kw + 1) * B_WORDS + colw) * 4);
#pragma unroll
                for (int mb = 0; mb < 3; mb++) {
                    int* c = cacc[mb][ni];
                    dp4a(c[0], aw[mb].x, b0.x); dp4a(c[0], aw[mb].y, b1.x);
                    dp4a(c[1], aw[mb].x, b0.y); dp4a(c[1], aw[mb].y, b1.y);
                    dp4a(c[2], aw[mb].x, b0.z); dp4a(c[2], aw[mb].y, b1.z);
                    dp4a(c[3], aw[mb].x, b0.w); dp4a(c[3], aw[mb].y, b1.w);
                }
            }
        }
    };

    // ---- prologue ----
    issue_chunk(0, 0);
    asm volatile("cp.async.commit_group;" ::: "memory");
    issue_chunk(1, 1);
    asm volatile("cp.async.commit_group;" ::: "memory");

    // ---- mainloop: one barrier per chunk ----
    int stg = 0;
    for (int i = 0; i < KCHUNKS; i++) {
        if (i + 1 < KCHUNKS)
            asm volatile("cp.async.wait_group 1;" ::: "memory");
        else
            asm volatile("cp.async.wait_group 0;" ::: "memory");
        __syncthreads();

        if (i + 2 < KCHUNKS) {
            int fstg = stg + 2; if (fstg >= NSTAGE) fstg -= NSTAGE;
            issue_chunk(i + 2, fstg);
            asm volatile("cp.async.commit_group;" ::: "memory");
        }

        if (wid < 4) compute_imma(stg);
        else         compute_dp4a(stg);

        if (++stg == NSTAGE) stg = 0;
    }

    // ---- epilogue ----
    const float alpha = *alpha_p;
    if (wid < 4) {
#pragma unroll
        for (int mi = 0; mi < 5; mi++) {
#pragma unroll
            for (int ni = 0; ni < 4; ni++) {
                const int row = m0 + mi * 16 + g;
                const int col = n0 + wsub * 32 + ni * 8 + 2 * tig;
                float2 v0, v1;
                v0.x = (float)cacc[mi][ni][0] * alpha;
                v0.y = (float)cacc[mi][ni][1] * alpha;
                v1.x = (float)cacc[mi][ni][2] * alpha;
                v1.y = (float)cacc[mi][ni][3] * alpha;
                *reinterpret_cast<float2*>(outB + (size_t)row * NDIM + col) = v0;
                *reinterpret_cast<float2*>(outB + (size_t)(row + 8) * NDIM + col) = v1;
            }
        }
    } else {
#pragma unroll
        for (int mb = 0; mb < 3; mb++) {
#pragma unroll
            for (int ni = 0; ni < 4; ni++) {
                const int row = m0 + dmB + mb * 8 + g;
                const int col = n0 + dnB + ni * 16 + tig * 4;
                float4 v;
                v.x = (float)cacc[mb][ni][0] * alpha;
                v.y = (float)cacc[mb][ni][1] * alpha;
                v.z = (float)cacc[mb][ni][2] * alpha;
                v.w = (float)cacc[mb][ni][3] * alpha;
                *reinterpret_cast<float4*>(outB + (size_t)row * NDIM + col) = v;
            }
        }
    }
}

extern "C" void kernel_launch(void* const* d_in, const int* in_sizes, int n_in,
                              void* d_out, int out_size) {
    const int* a32 = (const int*)d_in[0];
    const int* b32 = (const int*)d_in[1];
    const float* alpha = (const float*)(n_in > 2 ? d_in[2] : d_in[1]);
    for (int i = 0; i < n_in; i++) {
        const long long sz = in_sizes[i];
        if (sz == (long long)A_ELEMS)      a32 = (const int*)d_in[i];
        else if (sz == (long long)B_ELEMS) b32 = (const int*)d_in[i];
        else if (sz == 1)                  alpha = (const float*)d_in[i];
    }
    float* out = (float*)d_out;

    int8_t* a8 = nullptr;
    int8_t* bt = nullptr;
    cudaGetSymbolAddress((void**)&a8, g_a8);
    cudaGetSymbolAddress((void**)&bt, g_bt);

    static int smem_set = 0;
    if (!smem_set) {
        cudaFuncSetAttribute(bmm_i8_kernel,
                             cudaFuncAttributeMaxDynamicSharedMemorySize, SMEM_TOTAL);
        smem_set = 1;
    }

    conv_a_kernel<<<2048, 256>>>((const int4*)a32, (uint4*)a8, (long)(A_ELEMS / 16));
    conv_b_kernel<<<4096, 256>>>((const int4*)b32, (uint4*)bt);

    const int grid = 4 * (MDIM / MT) * (NDIM / NT);  // 1024 CTAs per launch
    for (int g = 0; g < 4; g++)
        bmm_i8_kernel<<<grid, THREADS, SMEM_TOTAL>>>(alpha, out, g * 4);
}

// round 17
// speedup vs baseline: 1.5944x; 1.0171x over previous
#include <cuda_runtime.h>
#include <cstdint>

// ---------------------------------------------------------------------------
// BMM_AB_I8_E_F32: C[b,m,n] = alpha * sum_k a[b,m,k]*b[b,k,n]
// B=16, M=1024, K=4096, N=4096.
//
// R2:  PTX target sm_103 (no 'a') -> no tcgen05; legacy mma.sync only.
// R6:  inputs serialized int32 -> int8 scratch conversion pre-pass.
// R8:  legacy IMMA ~267 MACs/cyc/SM; dp4a on fma pipe rt=1 (512/cyc/SM).
// R16: 80 IMMA rows / 48 dp4a rows: tensor span 4880 cyc/chunk binds, plus
//      ~1300 cyc fixed overhead per chunk (barrier + issue). 87% of the
//      combined-pipe ceiling (2.38ms GEMM ideal).
// R17: KT 64 -> 128 bytes (32 chunks instead of 64): halves the per-chunk
//      overhead term. A_STRIDE 144 (conflict-free ldmatrix/lds64),
//      NSTAGE=3, SMEM 106KB/CTA, occupancy 2 retained. Split stays 80/48.
// ---------------------------------------------------------------------------

#define BATCH   16
#define MDIM    1024
#define KDIM    4096
#define NDIM    4096

#define MT      128
#define NT      128
#define KT      128           // K bytes per pipeline chunk
#define KCHUNKS (KDIM / KT)   // 32
#define THREADS 256
#define NSTAGE  3

#define A_STRIDE 144                    // bytes per m-row in SMEM (128 + 16 pad)
#define A_STAGE  (128 * A_STRIDE)       // 18432
#define B_WORDS  132                    // k-word row stride in words
#define B_STAGE  (32 * B_WORDS * 4)     // 16896 (32 k-word rows per chunk)

#define OFF_A    0
#define OFF_B    (NSTAGE * A_STAGE)                 // 55296
#define SMEM_TOTAL (OFF_B + NSTAGE * B_STAGE)       // 105984

#define A_ELEMS ((size_t)BATCH * MDIM * KDIM)   // 67108864
#define B_ELEMS ((size_t)BATCH * KDIM * NDIM)   // 268435456
#define KWTOT   ((size_t)BATCH * (KDIM / 4))    // 16384 global k-word rows

__device__ int8_t g_a8[A_ELEMS];
__device__ int8_t g_bt[B_ELEMS];   // B k-word-major: word[gkw*N + n] = b[4gkw..+3][n]

// ---------------- conversions ----------------
__device__ __forceinline__ uint32_t pack4(int4 x) {
    uint32_t lo = __byte_perm((uint32_t)x.x, (uint32_t)x.y, 0x0040);
    uint32_t hi = __byte_perm((uint32_t)x.z, (uint32_t)x.w, 0x0040);
    return __byte_perm(lo, hi, 0x5410);
}

__global__ void __launch_bounds__(256)
conv_a_kernel(const int4* __restrict__ src, uint4* __restrict__ dst, long n16) {
    const long stride = (long)gridDim.x * blockDim.x;
    for (long i = (long)blockIdx.x * blockDim.x + threadIdx.x; i < n16; i += stride) {
        uint4 v;
        v.x = pack4(src[i * 4 + 0]);
        v.y = pack4(src[i * 4 + 1]);
        v.z = pack4(src[i * 4 + 2]);
        v.w = pack4(src[i * 4 + 3]);
        dst[i] = v;
    }
}

__global__ void __launch_bounds__(256)
conv_b_kernel(const int4* __restrict__ src, uint4* __restrict__ dst) {
    const long total = (long)KWTOT * (NDIM / 4);     // 16.7M
    const long stride = (long)gridDim.x * blockDim.x;
    for (long i = (long)blockIdx.x * blockDim.x + threadIdx.x; i < total; i += stride) {
        const long gkw = i >> 10;
        const int  n4  = (int)(i & 1023);
        const int4* s = src + (gkw * 4) * (NDIM / 4) + n4;
        int4 r0 = s[0];
        int4 r1 = s[NDIM / 4];
        int4 r2 = s[2 * (NDIM / 4)];
        int4 r3 = s[3 * (NDIM / 4)];
        uint32_t w0 = pack4(make_int4(r0.x, r1.x, r2.x, r3.x));
        uint32_t w1 = pack4(make_int4(r0.y, r1.y, r2.y, r3.y));
        uint32_t w2 = pack4(make_int4(r0.z, r1.z, r2.z, r3.z));
        uint32_t w3 = pack4(make_int4(r0.w, r1.w, r2.w, r3.w));
        dst[gkw * (NDIM / 4) + n4] = make_uint4(w0, w1, w2, w3);
    }
}

// ---------------- GEMM helpers ----------------
__device__ __forceinline__ uint32_t smem_u32(const void* p) {
    uint32_t a;
    asm("{ .reg .u64 t; cvta.to.shared.u64 t, %1; cvt.u32.u64 %0, t; }"
        : "=r"(a) : "l"(p));
    return a;
}

__device__ __forceinline__ void cpa16(uint32_t dst, const void* src) {
    asm volatile("cp.async.cg.shared.global [%0], [%1], 16;" :: "r"(dst), "l"(src));
}

__device__ __forceinline__ void ldmA(uint32_t a[4], uint32_t addr) {
    asm volatile("ldmatrix.sync.aligned.m8n8.x4.shared.b16 {%0,%1,%2,%3}, [%4];"
                 : "=r"(a[0]), "=r"(a[1]), "=r"(a[2]), "=r"(a[3]) : "r"(addr));
}

__device__ __forceinline__ uint32_t lds32(uint32_t addr) {
    uint32_t v;
    asm volatile("ld.shared.b32 %0, [%1];" : "=r"(v) : "r"(addr));
    return v;
}

__device__ __forceinline__ uint2 lds64(uint32_t addr) {
    uint2 v;
    asm volatile("ld.shared.v2.b32 {%0,%1}, [%2];" : "=r"(v.x), "=r"(v.y) : "r"(addr));
    return v;
}

__device__ __forceinline__ uint4 lds128(uint32_t addr) {
    uint4 v;
    asm volatile("ld.shared.v4.b32 {%0,%1,%2,%3}, [%4];"
                 : "=r"(v.x), "=r"(v.y), "=r"(v.z), "=r"(v.w) : "r"(addr));
    return v;
}

__device__ __forceinline__ void mma_s8(int c[4], const uint32_t a[4],
                                       uint32_t b0, uint32_t b1) {
    asm volatile(
        "mma.sync.aligned.m16n8k32.row.col.s32.s8.s8.s32 "
        "{%0,%1,%2,%3}, {%4,%5,%6,%7}, {%8,%9}, {%0,%1,%2,%3};"
        : "+r"(c[0]), "+r"(c[1]), "+r"(c[2]), "+r"(c[3])
        : "r"(a[0]), "r"(a[1]), "r"(a[2]), "r"(a[3]), "r"(b0), "r"(b1));
}

__device__ __forceinline__ void dp4a(int& c, uint32_t a, uint32_t b) {
    asm volatile("dp4a.s32.s32 %0, %1, %2, %0;" : "+r"(c) : "r"(a), "r"(b));
}

__global__ void __launch_bounds__(THREADS, 2)
bmm_i8_kernel(const float* __restrict__ alpha_p, float* __restrict__ out,
              int batch0)
{
    extern __shared__ char smem[];
    const uint32_t sbase = smem_u32(smem);

    const int tid  = threadIdx.x;
    const int wid  = tid >> 5;
    const int lane = tid & 31;
    const int g    = lane >> 2;
    const int tig  = lane & 3;

    // 256 tiles per batch (8 m x 32 n); this launch covers 4 batches
    const int bid   = blockIdx.x;
    const int batch = batch0 + (bid >> 8);
    const int rem   = bid & 255;
    const int m0    = (rem >> 5) * MT;
    const int n0    = (rem & 31) * NT;

    const int8_t*   aB  = g_a8 + (size_t)batch * MDIM * KDIM + (size_t)m0 * KDIM;
    const uint32_t* btB = reinterpret_cast<const uint32_t*>(g_bt)
                          + (size_t)batch * (KDIM / 4) * NDIM + n0;
    float* outB = out + (size_t)batch * MDIM * NDIM;

    // Roles (1 of each per SMSP per CTA):
    //  warps 0-3: IMMA on m[0:80), warp w -> cols w*32..+32 (5 m16 strips)
    //  warps 4-7: dp4a on m[80:128), 2x2 grid of 24m x 64n
    const int wsub = wid & 3;
    const int dmB  = 80 + (wsub >> 1) * 24;     // dp4a row base
    const int dnB  = (wsub & 1) * 64;           // dp4a col base

    int cacc[5][4][4];                          // IMMA all 5; dp4a first 3
#pragma unroll
    for (int i = 0; i < 5; i++)
#pragma unroll
        for (int j = 0; j < 4; j++)
#pragma unroll
            for (int r = 0; r < 4; r++) cacc[i][j][r] = 0;

    // cp.async: A = 128 rows x 128 B = 1024 16B-segs; B = 32 rows x 512 B = 1024 segs
    auto issue_chunk = [&](int chunk, int stg) {
        const int kk  = chunk * KT;
        const int kw0 = chunk * 32;
        const uint32_t sA = sbase + OFF_A + stg * A_STAGE;
        const uint32_t sB = sbase + OFF_B + stg * B_STAGE;
#pragma unroll
        for (int t = 0; t < 4; t++) {
            const int s = tid + t * THREADS;
            const int row = s >> 3;
            const int col = (s & 7) << 4;
            cpa16(sA + (uint32_t)(row * A_STRIDE + col),
                  aB + (size_t)row * KDIM + kk + col);
        }
#pragma unroll
        for (int t = 0; t < 4; t++) {
            const int s = tid + t * THREADS;
            const int brow = s >> 5;
            const int bc   = (s & 31) << 4;
            cpa16(sB + (uint32_t)(brow * (B_WORDS * 4) + bc),
                  (const char*)(btB + (size_t)(kw0 + brow) * NDIM) + bc);
        }
    };

    // IMMA warps: 80m x 32n per warp, 80 m16n8k32 per chunk (4 k32 steps).
    auto compute_imma = [&](int stg) {
        const uint32_t baseA = sbase + OFF_A + stg * A_STAGE;
        const uint32_t baseB = sbase + OFF_B + stg * B_STAGE;
        const int mrow = lane & 15;
        const int khl  = lane >> 4;
#pragma unroll
        for (int ks = 0; ks < 4; ks++) {
            uint32_t bf[4][2];
#pragma unroll
            for (int ni = 0; ni < 4; ni++) {
                const int col = wsub * 32 + ni * 8 + g;
                const int kwb = ks * 8 + tig;
                bf[ni][0] = lds32(baseB + (uint32_t)((kwb)     * B_WORDS + col) * 4);
                bf[ni][1] = lds32(baseB + (uint32_t)((kwb + 4) * B_WORDS + col) * 4);
            }
#pragma unroll
            for (int mi = 0; mi < 5; mi++) {
                uint32_t af[4];
                ldmA(af, baseA + (uint32_t)(mrow + mi * 16) * A_STRIDE
                               + (uint32_t)((ks * 2 + khl) * 16));
#pragma unroll
                for (int ni = 0; ni < 4; ni++)
                    mma_s8(cacc[mi][ni], af, bf[ni][0], bf[ni][1]);
            }
        }
    };

    // dp4a warps: 24m x 64n per warp; 1536 dp4a + 176 LDS per thread per chunk.
    auto compute_dp4a = [&](int stg) {
        const uint32_t baseA = sbase + OFF_A + stg * A_STAGE;
        const uint32_t baseB = sbase + OFF_B + stg * B_STAGE;
#pragma unroll
        for (int kwp = 0; kwp < 16; kwp++) {
            const int kw = 2 * kwp;
            uint2 aw[3];
#pragma unroll
            for (int mb = 0; mb < 3; mb++)
                aw[mb] = lds64(baseA + (uint32_t)(dmB + mb * 8 + g) * A_STRIDE
                                     + (uint32_t)(kw * 4));
#pragma unroll
            for (int ni = 0; ni < 4; ni++) {
                const int colw = dnB + ni * 16 + tig * 4;
                uint4 b0 = lds128(baseB + (uint32_t)((kw)     * B_WORDS + colw) * 4);
                uint4 b1 = lds128(baseB + (uint32_t)((kw + 1) * B_WORDS + colw) * 4);
#pragma unroll
                for (int mb = 0; mb < 3; mb++) {
                    int* c = cacc[mb][ni];
                    dp4a(c[0], aw[mb].x, b0.x); dp4a(c[0], aw[mb].y, b1.x);
                    dp4a(c[1], aw[mb].x, b0.y); dp4a(c[1], aw[mb].y, b1.y);
                    dp4a(c[2], aw[mb].x, b0.z); dp4a(c[2], aw[mb].y, b1.z);
                    dp4a(c[3], aw[mb].x, b0.w); dp4a(c[3], aw[mb].y, b1.w);
                }
            }
        }
    };

    // ---- prologue ----
    issue_chunk(0, 0);
    asm volatile("cp.async.commit_group;" ::: "memory");
    issue_chunk(1, 1);
    asm volatile("cp.async.commit_group;" ::: "memory");

    // ---- mainloop: one barrier per chunk ----
    int stg = 0;
    for (int i = 0; i < KCHUNKS; i++) {
        if (i + 1 < KCHUNKS)
            asm volatile("cp.async.wait_group 1;" ::: "memory");
        else
            asm volatile("cp.async.wait_group 0;" ::: "memory");
        __syncthreads();

        if (i + 2 < KCHUNKS) {
            int fstg = stg + 2; if (fstg >= NSTAGE) fstg -= NSTAGE;
            issue_chunk(i + 2, fstg);
            asm volatile("cp.async.commit_group;" ::: "memory");
        }

        if (wid < 4) compute_imma(stg);
        else         compute_dp4a(stg);

        if (++stg == NSTAGE) stg = 0;
    }

    // ---- epilogue ----
    const float alpha = *alpha_p;
    if (wid < 4) {
#pragma unroll
        for (int mi = 0; mi < 5; mi++) {
#pragma unroll
            for (int ni = 0; ni < 4; ni++) {
                const int row = m0 + mi * 16 + g;
                const int col = n0 + wsub * 32 + ni * 8 + 2 * tig;
                float2 v0, v1;
                v0.x = (float)cacc[mi][ni][0] * alpha;
                v0.y = (float)cacc[mi][ni][1] * alpha;
                v1.x = (float)cacc[mi][ni][2] * alpha;
                v1.y = (float)cacc[mi][ni][3] * alpha;
                *reinterpret_cast<float2*>(outB + (size_t)row * NDIM + col) = v0;
                *reinterpret_cast<float2*>(outB + (size_t)(row + 8) * NDIM + col) = v1;
            }
        }
    } else {
#pragma unroll
        for (int mb = 0; mb < 3; mb++) {
#pragma unroll
            for (int ni = 0; ni < 4; ni++) {
                const int row = m0 + dmB + mb * 8 + g;
                const int col = n0 + dnB + ni * 16 + tig * 4;
                float4 v;
                v.x = (float)cacc[mb][ni][0] * alpha;
                v.y = (float)cacc[mb][ni][1] * alpha;
                v.z = (float)cacc[mb][ni][2] * alpha;
                v.w = (float)cacc[mb][ni][3] * alpha;
                *reinterpret_cast<float4*>(outB + (size_t)row * NDIM + col) = v;
            }
        }
    }
}

extern "C" void kernel_launch(void* const* d_in, const int* in_sizes, int n_in,
                              void* d_out, int out_size) {
    const int* a32 = (const int*)d_in[0];
    const int* b32 = (const int*)d_in[1];
    const float* alpha = (const float*)(n_in > 2 ? d_in[2] : d_in[1]);
    for (int i = 0; i < n_in; i++) {
        const long long sz = in_sizes[i];
        if (sz == (long long)A_ELEMS)      a32 = (const int*)d_in[i];
        else if (sz == (long long)B_ELEMS) b32 = (const int*)d_in[i];
        else if (sz == 1)                  alpha = (const float*)d_in[i];
    }
    float* out = (float*)d_out;

    int8_t* a8 = nullptr;
    int8_t* bt = nullptr;
    cudaGetSymbolAddress((void**)&a8, g_a8);
    cudaGetSymbolAddress((void**)&bt, g_bt);

    static int smem_set = 0;
    if (!smem_set) {
        cudaFuncSetAttribute(bmm_i8_kernel,
                             cudaFuncAttributeMaxDynamicSharedMemorySize, SMEM_TOTAL);
        smem_set = 1;
    }

    conv_a_kernel<<<2048, 256>>>((const int4*)a32, (uint4*)a8, (long)(A_ELEMS / 16));
    conv_b_kernel<<<4096, 256>>>((const int4*)b32, (uint4*)bt);

    const int grid = 4 * (MDIM / MT) * (NDIM / NT);  // 1024 CTAs per launch
    for (int g = 0; g < 4; g++)
        bmm_i8_kernel<<<grid, THREADS, SMEM_TOTAL>>>(alpha, out, g * 4);
}